// round 14
// baseline (speedup 1.0000x reference)
#include <cuda_runtime.h>
#include <cuda_bf16.h>
#include <math.h>

// GCN: N<=100000, E<=1280000, 18 -> 32 -> 64 -> 2, log_softmax.
// Slot-CSR (deg<=64, Poisson(12.8)). 4 kernels + 1 memset.
// Half-warp-per-node, lane = feature pair (f32x2): LDG.64 gather + packed
// add.rn.f32x2 (MLP=4), shared-LDS W2 epilogue with packed fma.rn.f32x2.
// Round 13: epilogue constants read from smem in the tail (not hoisted into
// long-lived registers) + __launch_bounds__(256,6) -> occupancy 50% -> 62.5%.

#define MAXN 100000
#define SLOT_SHIFT 6
#define FULL 0xffffffffu

typedef unsigned long long u64;

__device__ int    g_cursor[MAXN];          // zeroed, becomes degree after scatter
__device__ int    g_csr[MAXN << SLOT_SHIFT];
__device__ float2 g_meta[MAXN];            // (dinv, bitcast deg)
__device__ float  g_p [MAXN * 32];         // dinv[i] * (x @ W1)[i]
__device__ float  g_hs[MAXN * 32];         // dinv[i] * relu(layer1)[i]

// ---------------- packed f32x2 helpers ----------------

__device__ __forceinline__ u64 ld2(const float* p) {
    u64 x; asm("ld.global.nc.b64 %0, [%1];" : "=l"(x) : "l"(p)); return x;
}
__device__ __forceinline__ void fadd2(u64& a, u64 x) {
    asm("add.rn.f32x2 %0, %0, %1;" : "+l"(a) : "l"(x));
}
__device__ __forceinline__ void ffma2(u64& d, u64 a, u64 b) {
    asm("fma.rn.f32x2 %0, %1, %2, %0;" : "+l"(d) : "l"(a), "l"(b));
}
__device__ __forceinline__ u64 pack2(float lo, float hi) {
    u64 r; asm("mov.b64 %0, {%1, %2};" : "=l"(r) : "f"(lo), "f"(hi)); return r;
}
__device__ __forceinline__ void unpack2(u64 v, float& lo, float& hi) {
    asm("mov.b64 {%0, %1}, %2;" : "=f"(lo), "=f"(hi) : "l"(v));
}

// half-warp gather: node i_me, lane covers features 2*hl, 2*hl+1.
// cmin = min(cnt of both nodes in the warp) -> unpredicated common loop;
// per-lane scalar tail covers the rest.
__device__ __forceinline__ u64 gather_half(const float* __restrict__ feat,
                                           int i_me, int hl, int cnt, int cmin) {
    const int4* cp4 = (const int4*)(g_csr + (i_me << SLOT_SHIFT));
    u64 a0 = ld2(feat + i_me * 32 + hl * 2);   // self loop (pre-scaled row)
    u64 a1 = 0ull, a2 = 0ull, a3 = 0ull;
    int full4 = cmin >> 2;
    for (int q = 0; q < full4; q++) {
        int4 j = __ldg(cp4 + q);
        fadd2(a0, ld2(feat + j.x * 32 + hl * 2));
        fadd2(a1, ld2(feat + j.y * 32 + hl * 2));
        fadd2(a2, ld2(feat + j.z * 32 + hl * 2));
        fadd2(a3, ld2(feat + j.w * 32 + hl * 2));
    }
    const int* cp = (const int*)cp4;
    for (int k = full4 * 4; k < cnt; k++) {
        int j = __ldg(cp + k);
        fadd2(a0, ld2(feat + j * 32 + hl * 2));
    }
    fadd2(a0, a1); fadd2(a2, a3); fadd2(a0, a2);
    return a0;
}

// ---------------- scatter edges into slot-CSR ----------------

__global__ void k_scatter(const int* __restrict__ src, const int* __restrict__ dst, int e) {
    int i = blockIdx.x * blockDim.x + threadIdx.x;
    if (i < e) {
        int d = dst[i];
        int p = atomicAdd(&g_cursor[d], 1);
        g_csr[(d << SLOT_SHIFT) + p] = src[i];
    }
}

// ---------- meta (dinv,deg) + xw1 pre-scaled: g_p = dinv * (x @ W1) ----------

__global__ void __launch_bounds__(256) k_meta_xw1(const float* __restrict__ x,
                                                  const float* __restrict__ W1, int n) {
    __shared__ float sW1[18 * 32];
    __shared__ float sdinv[256];
    for (int i = threadIdx.x; i < 18 * 32; i += blockDim.x) sW1[i] = W1[i];

    int t  = threadIdx.x;
    int i0 = blockIdx.x * 256;
    int i  = i0 + t;
    float di = 0.f;
    if (i < n) {
        int d = g_cursor[i];
        di = rsqrtf((float)(d + 1));            // +1 self loop
        g_meta[i] = make_float2(di, __int_as_float(d));
    }
    sdinv[t] = di;
    __syncthreads();

    int lane = t & 31;
    int w    = t >> 5;
    int base = i0 + w * 32;
    #pragma unroll 1
    for (int q = 0; q < 32; q++) {
        int node = base + q;
        if (node >= n) break;
        float xv = (lane < 18) ? __ldg(&x[node * 18 + lane]) : 0.f;
        float acc = 0.f;
        #pragma unroll
        for (int k = 0; k < 18; k++) {
            float xk = __shfl_sync(FULL, xv, k);
            acc = fmaf(xk, sW1[k * 32 + lane], acc);
        }
        g_p[node * 32 + lane] = sdinv[w * 32 + q] * acc;
    }
}

// ---- agg1: half-warp per node. g_hs = dinv * relu(di*agg(g_p) + b1) ----

__global__ void __launch_bounds__(256, 6) k_agg1(const float* __restrict__ b1, int n) {
    __shared__ __align__(16) float sb1[32];
    if (threadIdx.x < 32) sb1[threadIdx.x] = b1[threadIdx.x];
    __syncthreads();

    int lane = threadIdx.x & 31;
    int hl   = lane & 15;
    bool isB = lane >= 16;
    int warp = (blockIdx.x * blockDim.x + threadIdx.x) >> 5;
    int nw   = (gridDim.x * blockDim.x) >> 5;
    int npair = (n + 1) >> 1;

    for (int p = warp; p < npair; p += nw) {
        int iA  = 2 * p;
        int iBr = 2 * p + 1;
        int i_me = isB ? ((iBr < n) ? iBr : iA) : iA;
        float2 meta = __ldg(&g_meta[i_me]);
        float di = meta.x;
        int cnt  = __float_as_int(meta.y);
        int cntO = __shfl_xor_sync(FULL, cnt, 16);
        u64 s = gather_half(g_p, i_me, hl, cnt, min(cnt, cntO));
        float s_lo, s_hi;
        unpack2(s, s_lo, s_hi);
        float2 bb = *(const float2*)(sb1 + 2 * hl);
        float h_lo = di * fmaxf(fmaf(di, s_lo, bb.x), 0.f);
        float h_hi = di * fmaxf(fmaf(di, s_hi, bb.y), 0.f);
        *(float2*)(g_hs + i_me * 32 + hl * 2) = make_float2(h_lo, h_hi);
    }
}

// ---- agg2: half-warp gather + shared-LDS W2 epilogue + FC + log_softmax ----

__global__ void __launch_bounds__(256, 6) k_agg2(const float* __restrict__ W2,
                                                 const float* __restrict__ b2,
                                                 const float* __restrict__ Wfc,
                                                 const float* __restrict__ bfc,
                                                 float* __restrict__ out, int n) {
    __shared__ __align__(16) float sW2[32 * 64];
    __shared__ __align__(16) float sb2[64];
    __shared__ float sWfc[128];
    __shared__ float sbfc[2];
    for (int i = threadIdx.x; i < 32 * 64; i += blockDim.x) sW2[i] = W2[i];
    if (threadIdx.x < 128) sWfc[threadIdx.x] = Wfc[threadIdx.x];
    if (threadIdx.x < 64)  sb2[threadIdx.x]  = b2[threadIdx.x];
    if (threadIdx.x < 2)   sbfc[threadIdx.x] = bfc[threadIdx.x];
    __syncthreads();

    int lane  = threadIdx.x & 31;
    int hl    = lane & 15;
    int hbase = lane & 16;
    bool isB  = hbase != 0;
    int q4    = hl * 4;                 // this lane owns cols q4..q4+3 of its node

    int warp = (blockIdx.x * blockDim.x + threadIdx.x) >> 5;
    int nw   = (gridDim.x * blockDim.x) >> 5;
    int npair = (n + 1) >> 1;

    for (int p = warp; p < npair; p += nw) {
        int iA  = 2 * p;
        int iBr = 2 * p + 1;
        int i_me = isB ? ((iBr < n) ? iBr : iA) : iA;
        float2 meta = __ldg(&g_meta[i_me]);
        float di = meta.x;
        int cnt  = __float_as_int(meta.y);
        int cntO = __shfl_xor_sync(FULL, cnt, 16);
        u64 s = gather_half(g_hs, i_me, hl, cnt, min(cnt, cntO));
        float t_lo, t_hi;
        unpack2(s, t_lo, t_hi);
        t_lo *= di;
        t_hi *= di;

        // epilogue: each l-step broadcasts features (2l, 2l+1) within the half
        // and does 4 packed FMAs; W2 LDS.128 addresses are identical across
        // halves (same l, same q4 pattern) -> dedup'd, serves both nodes.
        u64 c01 = 0ull, c23 = 0ull;     // cols (q4,q4+1), (q4+2,q4+3)
        #pragma unroll
        for (int l = 0; l < 16; l++) {
            float tl = __shfl_sync(FULL, t_lo, hbase + l);
            float th = __shfl_sync(FULL, t_hi, hbase + l);
            ulonglong2 W0 = *(const ulonglong2*)(sW2 + (2 * l) * 64 + q4);
            ulonglong2 W1 = *(const ulonglong2*)(sW2 + (2 * l + 1) * 64 + q4);
            u64 tl2 = pack2(tl, tl);
            u64 th2 = pack2(th, th);
            ffma2(c01, tl2, W0.x);
            ffma2(c23, tl2, W0.y);
            ffma2(c01, th2, W1.x);
            ffma2(c23, th2, W1.y);
        }
        float a0, a1, a2, a3;
        unpack2(c01, a0, a1);
        unpack2(c23, a2, a3);
        // epilogue constants read HERE (once per pair) instead of hoisted
        float4 bb4 = *(const float4*)(sb2 + q4);
        float h0 = fmaxf(a0 + bb4.x, 0.f);
        float h1 = fmaxf(a1 + bb4.y, 0.f);
        float h2 = fmaxf(a2 + bb4.z, 0.f);
        float h3 = fmaxf(a3 + bb4.w, 0.f);
        float p0 = h0 * sWfc[(q4 + 0) * 2] + h1 * sWfc[(q4 + 1) * 2]
                 + h2 * sWfc[(q4 + 2) * 2] + h3 * sWfc[(q4 + 3) * 2];
        float p1 = h0 * sWfc[(q4 + 0) * 2 + 1] + h1 * sWfc[(q4 + 1) * 2 + 1]
                 + h2 * sWfc[(q4 + 2) * 2 + 1] + h3 * sWfc[(q4 + 3) * 2 + 1];
        // reduce within each 16-lane half (xor offsets stay inside the half)
        #pragma unroll
        for (int o = 8; o; o >>= 1) {
            p0 += __shfl_xor_sync(FULL, p0, o);
            p1 += __shfl_xor_sync(FULL, p1, o);
        }
        if (hl == 0 && (!isB || iBr < n)) {
            float l0 = p0 + sbfc[0];
            float l1 = p1 + sbfc[1];
            float m  = fmaxf(l0, l1);
            float lse = m + logf(expf(l0 - m) + expf(l1 - m));
            ((float2*)out)[i_me] = make_float2(l0 - lse, l1 - lse);
        }
    }
}

// ---------------- launch ----------------

extern "C" void kernel_launch(void* const* d_in, const int* in_sizes, int n_in,
                              void* d_out, int out_size) {
    const float* x   = (const float*)d_in[0];
    const int*   ei  = (const int*)d_in[1];
    const float* W1  = (const float*)d_in[2];
    const float* b1  = (const float*)d_in[3];
    const float* W2  = (const float*)d_in[4];
    const float* b2  = (const float*)d_in[5];
    const float* Wfc = (const float*)d_in[6];
    const float* bfc = (const float*)d_in[7];
    float* out = (float*)d_out;

    int n = in_sizes[0] / 18;
    int e = in_sizes[1] / 2;
    const int* src = ei;
    const int* dst = ei + e;

    void* curp = nullptr;
    cudaGetSymbolAddress(&curp, g_cursor);
    cudaMemsetAsync(curp, 0, n * sizeof(int));

    k_scatter<<<(e + 255) / 256, 256>>>(src, dst, e);
    k_meta_xw1<<<(n + 255) / 256, 256>>>(x, W1, n);
    k_agg1<<<1184, 256>>>(b1, n);
    k_agg2<<<1184, 256>>>(W2, b2, Wfc, bfc, out, n);
}